// round 14
// baseline (speedup 1.0000x reference)
#include <cuda_runtime.h>
typedef unsigned u32; typedef unsigned long long u64;
#define QQ 32768
#define HD 96
#define WD 96
#define HWP 9216

__device__ float g_feat[(size_t)2*HWP*64];
__device__ float g_mod[(size_t)2*QQ*1024];   // layout [q][c*16+k]

__device__ __forceinline__ u64 pack2(float lo, float hi) {
    u64 r; asm("mov.b64 %0, {%1, %2};" : "=l"(r) : "f"(lo), "f"(hi)); return r;
}
__device__ __forceinline__ void unpack2(u64 v, float& lo, float& hi) {
    asm("mov.b64 {%0, %1}, %2;" : "=f"(lo), "=f"(hi) : "l"(v));
}
__device__ __forceinline__ void ffma2(u64& d, u64 a, u64 b) {
    asm("fma.rn.f32x2 %0, %1, %2, %0;" : "+l"(d) : "l"(a), "l"(b));
}

__device__ __forceinline__ void geom(float c0, float c1, int k, int& pix,
                                     float& rel0, float& rel1, float& area) {
    const float rs = 1.0f/96.0f;
    float sy = (float)(2*(k>>2)-3), sx = (float)(2*(k&3)-3);
    float cs0 = __fadd_rn(__fadd_rn(c0, __fmul_rn(sy,rs)), 1e-6f);
    float cs1 = __fadd_rn(__fadd_rn(c1, __fmul_rn(sx,rs)), 1e-6f);
    cs0 = fminf(0.999999f, fmaxf(-0.999999f, cs0));
    cs1 = fminf(0.999999f, fmaxf(-0.999999f, cs1));
    float py = __fadd_rn(__fmul_rn(__fmul_rn(__fadd_rn(cs0,1.f),96.f),0.5f),-0.5f);
    float px = __fadd_rn(__fmul_rn(__fmul_rn(__fadd_rn(cs1,1.f),96.f),0.5f),-0.5f);
    int iy = min(HD-1, max(0,(int)rintf(py)));
    int ix = min(WD-1, max(0,(int)rintf(px)));
    pix = iy*WD + ix;
    float qcy = __fadd_rn(-1.f, __fmul_rn(__fadd_rn(__fmul_rn(2.f,(float)iy),1.f), rs));
    float qcx = __fadd_rn(-1.f, __fmul_rn(__fadd_rn(__fmul_rn(2.f,(float)ix),1.f), rs));
    rel0 = __fmul_rn(__fsub_rn(c0,qcy),96.f);
    rel1 = __fmul_rn(__fsub_rn(c1,qcx),96.f);
    area = __fadd_rn(fabsf(__fmul_rn(rel0,rel1)), 1e-9f);
}

// ---------------- conv (frozen) ----------------
__global__ void conv_kernel(const float* __restrict__ inp, const float* __restrict__ w_enc,
                            const float* __restrict__ b_enc) {
    int idx = blockIdx.x*blockDim.x + threadIdx.x;
    if (idx >= 2*HWP*16) return;
    int p = idx % HWP, o4 = (idx / HWP) & 15, b = idx / (HWP*16);
    int y = p/WD, x = p%WD;
    float pin[27];
#pragma unroll
    for (int i = 0; i < 3; i++) {
        const float* ip = inp + (b*3+i)*HWP;
#pragma unroll
        for (int dy = 0; dy < 3; dy++) {
#pragma unroll
            for (int dx = 0; dx < 3; dx++) {
                int yy = y+dy-1, xx = x+dx-1;
                bool ok = (yy>=0 && yy<HD && xx>=0 && xx<WD);
                pin[i*9+dy*3+dx] = ok ? ip[yy*WD+xx] : 0.f;
            }
        }
    }
    float4 acc;
    float* a = (float*)&acc;
#pragma unroll
    for (int oo = 0; oo < 4; oo++) {
        int o = o4*4 + oo;
        float s = b_enc[o];
        const float* wp = w_enc + o*27;
#pragma unroll
        for (int i = 0; i < 27; i++) s = fmaf(pin[i], wp[i], s);
        a[oo] = s;
    }
    *(float4*)(g_feat + (size_t)(b*HWP+p)*64 + o4*4) = acc;
}

// ---------------- meta kernel ----------------
#define MS_WM1 0
#define MS_BM1 2112
#define MS_H   2176
#define MS_WC  10624
#define MS_BM2 18816
#define MS_TOT 18944
#define MS_BYTES (MS_TOT*4)

__global__ void __launch_bounds__(256, 2) meta_kernel(
    const float* __restrict__ coord, const float* __restrict__ cell,
    const float* __restrict__ w_m1, const float* __restrict__ b_m1,
    const float* __restrict__ w_m2, const float* __restrict__ b_m2) {
    extern __shared__ float sm[];
    const int t = threadIdx.x;
    for (int i = t; i < 528; i += 256)
        ((float4*)(sm + MS_WM1))[i] = ((const float4*)w_m1)[i];
    if (t < 64) sm[MS_BM1+t] = b_m1[t];
    __syncthreads();

    {
        int ql = t>>1, jh = (t&1)*32;
        int q = blockIdx.x*128 + ql;
        float c0 = coord[2*q], c1 = coord[2*q+1];
        float meta[33];
        meta[32] = __fmul_rn(cell[2*q], 96.f);
#pragma unroll
        for (int k = 0; k < 16; k++) {
            int pix; float r0, r1, ar; geom(c0, c1, k, pix, r0, r1, ar);
            meta[2*k] = r0; meta[2*k+1] = r1;
        }
        u64 acc[16];
#pragma unroll
        for (int p = 0; p < 16; p++)
            acc[p] = pack2(sm[MS_BM1+jh+2*p], sm[MS_BM1+jh+2*p+1]);
        for (int i = 0; i < 33; i++) {
            float m = meta[i]; u64 mm = pack2(m, m);
            const ulonglong2* wp = (const ulonglong2*)(sm + MS_WM1 + i*64 + jh);
#pragma unroll
            for (int p = 0; p < 8; p++) {
                ulonglong2 w = wp[p];
                ffma2(acc[2*p], mm, w.x); ffma2(acc[2*p+1], mm, w.y);
            }
        }
#pragma unroll
        for (int p = 0; p < 16; p++) {
            float a, b; unpack2(acc[p], a, b);
            sm[MS_H + (jh+2*p)*132 + ql] = fmaxf(a, 0.f);
            sm[MS_H + (jh+2*p+1)*132 + ql] = fmaxf(b, 0.f);
        }
    }

    const int qt = t>>4, nt = t&15;
    const int q0 = qt*8;
    const int qg = blockIdx.x*128 + q0;
    for (int nb = 0; nb < 8; nb++) {
        __syncthreads();
        for (int i = t; i < 2048; i += 256) {
            int c = i>>5, n4 = (i&31)*4;
            *(float4*)(sm + MS_WC + c*128 + n4) = *(const float4*)(w_m2 + c*1024 + nb*128 + n4);
        }
        if (t < 32) *(float4*)(sm + MS_BM2 + t*4) = *(const float4*)(b_m2 + nb*128 + t*4);
        __syncthreads();
        u64 acc[4][8];
#pragma unroll
        for (int p = 0; p < 4; p++)
#pragma unroll
            for (int j = 0; j < 8; j++) acc[p][j] = 0ull;
#pragma unroll 8
        for (int c = 0; c < 64; c++) {
            ulonglong2 xA = *(const ulonglong2*)(sm + MS_H + c*132 + q0);
            ulonglong2 xB = *(const ulonglong2*)(sm + MS_H + c*132 + q0 + 4);
            float4 wa = *(const float4*)(sm + MS_WC + c*128 + nt*4);
            float4 wb = *(const float4*)(sm + MS_WC + c*128 + 64 + nt*4);
            u64 wd[8];
            wd[0]=pack2(wa.x,wa.x); wd[1]=pack2(wa.y,wa.y); wd[2]=pack2(wa.z,wa.z); wd[3]=pack2(wa.w,wa.w);
            wd[4]=pack2(wb.x,wb.x); wd[5]=pack2(wb.y,wb.y); wd[6]=pack2(wb.z,wb.z); wd[7]=pack2(wb.w,wb.w);
#pragma unroll
            for (int j = 0; j < 8; j++) {
                ffma2(acc[0][j], xA.x, wd[j]);
                ffma2(acc[1][j], xA.y, wd[j]);
                ffma2(acc[2][j], xB.x, wd[j]);
                ffma2(acc[3][j], xB.y, wd[j]);
            }
        }
#pragma unroll
        for (int p = 0; p < 4; p++) {
            float4 lo0, hi0, lo1, hi1;
            float* l0 = (float*)&lo0; float* h0 = (float*)&hi0;
            float* l1 = (float*)&lo1; float* h1 = (float*)&hi1;
#pragma unroll
            for (int j = 0; j < 4; j++) {
                float a, b; unpack2(acc[p][j], a, b);
                float bz = sm[MS_BM2 + nt*4 + j];
                l0[j] = a + bz; h0[j] = b + bz;
                unpack2(acc[p][4+j], a, b);
                bz = sm[MS_BM2 + 64 + nt*4 + j];
                l1[j] = a + bz; h1[j] = b + bz;
            }
            size_t r0o = (size_t)(qg + 2*p)*1024 + nb*128 + nt*4;
            size_t r1o = (size_t)(qg + 2*p + 1)*1024 + nb*128 + nt*4;
            *(float4*)(g_mod + r0o) = lo0;       *(float4*)(g_mod + r0o + 64) = lo1;
            *(float4*)(g_mod + r1o) = hi0;       *(float4*)(g_mod + r1o + 64) = hi1;
        }
    }
}

// ---------------- imnet kernel ----------------
#define IS_X    0
#define IS_WT   9240
#define IS_BI1  13720
#define IS_WI2  13784
#define IS_AREA 14040
#define IS_TOT  14168
#define IS_BYTES (IS_TOT*4)
#define IS_PRED 0
#define IS_PW   4096

__global__ void __launch_bounds__(128, 4) imnet_kernel(
    const float* __restrict__ inp, const float* __restrict__ coord,
    const float* __restrict__ cell, const float* __restrict__ w_i1,
    const float* __restrict__ b_i1, const float* __restrict__ w_i2,
    const float* __restrict__ b_i2, float* __restrict__ out) {
    extern __shared__ float sm[];
    const int t = threadIdx.x;
    for (int i = t; i < 1120; i += 128)
        ((float4*)(sm + IS_WT))[i] = ((const float4*)w_i1)[i];
    if (t < 64) {
        sm[IS_BI1+t] = b_i1[t];
        float4 v; v.x = w_i2[t*3]; v.y = w_i2[t*3+1]; v.z = w_i2[t*3+2]; v.w = 0.f;
        *(float4*)(sm + IS_WI2 + t*4) = v;
    }
    const int qi = t>>4, k = t&15;
    const int rt = t>>3, nt = t&7;
    const int r0 = rt*8;

    for (int tile = 0; tile < 2; tile++) {
        if (tile) __syncthreads();
        const int q = blockIdx.x*16 + tile*8 + qi, b = q>>15;

        // ---- stage mod[8q][1024] into X region, coalesced ----
        {
            const float4* msrc =
                (const float4*)(g_mod + (size_t)(blockIdx.x*16 + tile*8)*1024);
            float4* mdst = (float4*)(sm + IS_X);
#pragma unroll
            for (int i = 0; i < 16; i++) mdst[t + i*128] = msrc[t + i*128];
        }
        __syncthreads();

        float modr[64];
#pragma unroll
        for (int c = 0; c < 64; c++) modr[c] = sm[IS_X + qi*1024 + c*16 + k];
        __syncthreads();

        // ---- build X row ----
        {
            float c0 = coord[2*q], c1 = coord[2*q+1];
            float relc = __fmul_rn(cell[2*q], 96.f);
            int pix; float rel0, rel1, area;
            geom(c0, c1, k, pix, rel0, rel1, area);
            sm[IS_AREA + t] = area;
            const float4* fb = (const float4*)(g_feat + (size_t)(b*HWP+pix)*64);
#pragma unroll
            for (int g = 0; g < 16; g++) {
                float4 f = fb[g];
                sm[IS_X + (4*g+0)*132 + t] = f.x * modr[4*g+0];
                sm[IS_X + (4*g+1)*132 + t] = f.y * modr[4*g+1];
                sm[IS_X + (4*g+2)*132 + t] = f.z * modr[4*g+2];
                sm[IS_X + (4*g+3)*132 + t] = f.w * modr[4*g+3];
            }
            sm[IS_X + 64*132 + t] = inp[(b*3+0)*HWP + pix];
            sm[IS_X + 65*132 + t] = inp[(b*3+1)*HWP + pix];
            sm[IS_X + 66*132 + t] = inp[(b*3+2)*HWP + pix];
            sm[IS_X + 67*132 + t] = rel0;
            sm[IS_X + 68*132 + t] = rel1;
            sm[IS_X + 69*132 + t] = relc;
        }
        __syncthreads();

        // ---- GEMM 128r x 64n, 8r x 8n tiles ----
        u64 acc[4][8];
#pragma unroll
        for (int p = 0; p < 4; p++)
#pragma unroll
            for (int j = 0; j < 8; j++) acc[p][j] = 0ull;
#pragma unroll 10
        for (int c = 0; c < 70; c++) {
            ulonglong2 xA = *(const ulonglong2*)(sm + IS_X + c*132 + r0);
            ulonglong2 xB = *(const ulonglong2*)(sm + IS_X + c*132 + r0 + 4);
            float4 wa = *(const float4*)(sm + IS_WT + c*64 + nt*4);
            float4 wb = *(const float4*)(sm + IS_WT + c*64 + 32 + nt*4);
            u64 wd[8];
            wd[0]=pack2(wa.x,wa.x); wd[1]=pack2(wa.y,wa.y); wd[2]=pack2(wa.z,wa.z); wd[3]=pack2(wa.w,wa.w);
            wd[4]=pack2(wb.x,wb.x); wd[5]=pack2(wb.y,wb.y); wd[6]=pack2(wb.z,wb.z); wd[7]=pack2(wb.w,wb.w);
#pragma unroll
            for (int j = 0; j < 8; j++) {
                ffma2(acc[0][j], xA.x, wd[j]);
                ffma2(acc[1][j], xA.y, wd[j]);
                ffma2(acc[2][j], xB.x, wd[j]);
                ffma2(acc[3][j], xB.y, wd[j]);
            }
        }
        __syncthreads();

        // ---- layer 2 partials ----
#pragma unroll
        for (int p = 0; p < 4; p++) {
            float pr0[3] = {0.f,0.f,0.f}, pr1[3] = {0.f,0.f,0.f};
#pragma unroll
            for (int j = 0; j < 8; j++) {
                int n = (j < 4) ? (nt*4 + j) : (32 + nt*4 + j - 4);
                float a, bv; unpack2(acc[p][j], a, bv);
                float bz = sm[IS_BI1 + n];
                float a0 = fmaxf(a + bz, 0.f), a1 = fmaxf(bv + bz, 0.f);
                float4 w2 = *(const float4*)(sm + IS_WI2 + n*4);
                pr0[0] = fmaf(a0, w2.x, pr0[0]); pr0[1] = fmaf(a0, w2.y, pr0[1]); pr0[2] = fmaf(a0, w2.z, pr0[2]);
                pr1[0] = fmaf(a1, w2.x, pr1[0]); pr1[1] = fmaf(a1, w2.y, pr1[1]); pr1[2] = fmaf(a1, w2.z, pr1[2]);
            }
            float4 v0; v0.x = pr0[0]; v0.y = pr0[1]; v0.z = pr0[2]; v0.w = 0.f;
            float4 v1; v1.x = pr1[0]; v1.y = pr1[1]; v1.z = pr1[2]; v1.w = 0.f;
            *(float4*)(sm + IS_PRED + ((r0 + 2*p)*8 + nt)*4) = v0;
            *(float4*)(sm + IS_PRED + ((r0 + 2*p + 1)*8 + nt)*4) = v1;
        }
        __syncthreads();

        // ---- per-row reduce + area blend ----
        {
            float s0 = 0.f, s1 = 0.f, s2 = 0.f;
#pragma unroll
            for (int n = 0; n < 8; n++) {
                float4 v = *(const float4*)(sm + IS_PRED + (t*8 + n)*4);
                s0 += v.x; s1 += v.y; s2 += v.z;
            }
            float tot = 0.f;
#pragma unroll
            for (int kk = 0; kk < 16; kk++) tot += sm[IS_AREA + qi*16 + kk];
            float wgt = __fdiv_rn(sm[IS_AREA + qi*16 + (15-k)], tot);
            float4 v; v.x = s0*wgt; v.y = s1*wgt; v.z = s2*wgt; v.w = 0.f;
            __syncthreads();
            *(float4*)(sm + IS_PW + t*4) = v;
        }
        __syncthreads();
        if (t < 24) {
            int qi2 = t/3, ch = t%3;
            float s = 0.f;
#pragma unroll
            for (int kk = 0; kk < 16; kk++) s += sm[IS_PW + (qi2*16 + kk)*4 + ch];
            out[(size_t)(blockIdx.x*16 + tile*8 + qi2)*3 + ch] = s;
        }
    }
}

extern "C" void kernel_launch(void* const* d_in, const int* in_sizes, int n_in,
                              void* d_out, int out_size) {
    const float* inp   = (const float*)d_in[0];
    const float* coord = (const float*)d_in[1];
    const float* cell  = (const float*)d_in[2];
    const float* w_enc = (const float*)d_in[3];
    const float* b_enc = (const float*)d_in[4];
    const float* w_m1  = (const float*)d_in[5];
    const float* b_m1  = (const float*)d_in[6];
    const float* w_m2  = (const float*)d_in[7];
    const float* b_m2  = (const float*)d_in[8];
    const float* w_i1  = (const float*)d_in[9];
    const float* b_i1  = (const float*)d_in[10];
    const float* w_i2  = (const float*)d_in[11];
    const float* b_i2  = (const float*)d_in[12];
    float* out = (float*)d_out;

    cudaFuncSetAttribute(meta_kernel, cudaFuncAttributeMaxDynamicSharedMemorySize, MS_BYTES);
    cudaFuncSetAttribute(imnet_kernel, cudaFuncAttributeMaxDynamicSharedMemorySize, IS_BYTES);

    conv_kernel<<<(2*HWP*16 + 255)/256, 256>>>(inp, w_enc, b_enc);
    meta_kernel<<<512, 256, MS_BYTES>>>(coord, cell, w_m1, b_m1, w_m2, b_m2);
    imnet_kernel<<<4096, 128, IS_BYTES>>>(inp, coord, cell, w_i1, b_i1, w_i2, b_i2, out);
}

// round 15
// speedup vs baseline: 1.0831x; 1.0831x over previous
#include <cuda_runtime.h>
typedef unsigned u32; typedef unsigned long long u64;
#define QQ 32768
#define HD 96
#define WD 96
#define HWP 9216

__device__ float g_feat[(size_t)2*HWP*64];   // layout [b][y][c4][x][4c]
__device__ float g_mod[(size_t)2*QQ*1024];   // layout [q][c*16+k]

__device__ __forceinline__ u64 pack2(float lo, float hi) {
    u64 r; asm("mov.b64 %0, {%1, %2};" : "=l"(r) : "f"(lo), "f"(hi)); return r;
}
__device__ __forceinline__ void unpack2(u64 v, float& lo, float& hi) {
    asm("mov.b64 {%0, %1}, %2;" : "=f"(lo), "=f"(hi) : "l"(v));
}
__device__ __forceinline__ void ffma2(u64& d, u64 a, u64 b) {
    asm("fma.rn.f32x2 %0, %1, %2, %0;" : "+l"(d) : "l"(a), "l"(b));
}

__device__ __forceinline__ void geom(float c0, float c1, int k, int& pix,
                                     float& rel0, float& rel1, float& area) {
    const float rs = 1.0f/96.0f;
    float sy = (float)(2*(k>>2)-3), sx = (float)(2*(k&3)-3);
    float cs0 = __fadd_rn(__fadd_rn(c0, __fmul_rn(sy,rs)), 1e-6f);
    float cs1 = __fadd_rn(__fadd_rn(c1, __fmul_rn(sx,rs)), 1e-6f);
    cs0 = fminf(0.999999f, fmaxf(-0.999999f, cs0));
    cs1 = fminf(0.999999f, fmaxf(-0.999999f, cs1));
    float py = __fadd_rn(__fmul_rn(__fmul_rn(__fadd_rn(cs0,1.f),96.f),0.5f),-0.5f);
    float px = __fadd_rn(__fmul_rn(__fmul_rn(__fadd_rn(cs1,1.f),96.f),0.5f),-0.5f);
    int iy = min(HD-1, max(0,(int)rintf(py)));
    int ix = min(WD-1, max(0,(int)rintf(px)));
    pix = iy*WD + ix;
    float qcy = __fadd_rn(-1.f, __fmul_rn(__fadd_rn(__fmul_rn(2.f,(float)iy),1.f), rs));
    float qcx = __fadd_rn(-1.f, __fmul_rn(__fadd_rn(__fmul_rn(2.f,(float)ix),1.f), rs));
    rel0 = __fmul_rn(__fsub_rn(c0,qcy),96.f);
    rel1 = __fmul_rn(__fsub_rn(c1,qcx),96.f);
    area = __fadd_rn(fabsf(__fmul_rn(rel0,rel1)), 1e-9f);
}

// ---------------- conv: store to [b][y][c4][x][4c] layout ----------------
__global__ void conv_kernel(const float* __restrict__ inp, const float* __restrict__ w_enc,
                            const float* __restrict__ b_enc) {
    int idx = blockIdx.x*blockDim.x + threadIdx.x;
    if (idx >= 2*HWP*16) return;
    int p = idx % HWP, o4 = (idx / HWP) & 15, b = idx / (HWP*16);
    int y = p/WD, x = p%WD;
    float pin[27];
#pragma unroll
    for (int i = 0; i < 3; i++) {
        const float* ip = inp + (b*3+i)*HWP;
#pragma unroll
        for (int dy = 0; dy < 3; dy++) {
#pragma unroll
            for (int dx = 0; dx < 3; dx++) {
                int yy = y+dy-1, xx = x+dx-1;
                bool ok = (yy>=0 && yy<HD && xx>=0 && xx<WD);
                pin[i*9+dy*3+dx] = ok ? ip[yy*WD+xx] : 0.f;
            }
        }
    }
    float4 acc;
    float* a = (float*)&acc;
#pragma unroll
    for (int oo = 0; oo < 4; oo++) {
        int o = o4*4 + oo;
        float s = b_enc[o];
        const float* wp = w_enc + o*27;
#pragma unroll
        for (int i = 0; i < 27; i++) s = fmaf(pin[i], wp[i], s);
        a[oo] = s;
    }
    *(float4*)(g_feat + (size_t)b*HWP*64 + ((size_t)(y*16 + o4)*WD + x)*4) = acc;
}

// ---------------- meta kernel (frozen R13) ----------------
#define MS_WM1 0
#define MS_BM1 2112
#define MS_H   2176
#define MS_WC  10624
#define MS_BM2 18816
#define MS_TOT 18944
#define MS_BYTES (MS_TOT*4)

__global__ void __launch_bounds__(256, 2) meta_kernel(
    const float* __restrict__ coord, const float* __restrict__ cell,
    const float* __restrict__ w_m1, const float* __restrict__ b_m1,
    const float* __restrict__ w_m2, const float* __restrict__ b_m2) {
    extern __shared__ float sm[];
    const int t = threadIdx.x;
    for (int i = t; i < 528; i += 256)
        ((float4*)(sm + MS_WM1))[i] = ((const float4*)w_m1)[i];
    if (t < 64) sm[MS_BM1+t] = b_m1[t];
    __syncthreads();

    {
        int ql = t>>1, jh = (t&1)*32;
        int q = blockIdx.x*128 + ql;
        float c0 = coord[2*q], c1 = coord[2*q+1];
        float meta[33];
        meta[32] = __fmul_rn(cell[2*q], 96.f);
#pragma unroll
        for (int k = 0; k < 16; k++) {
            int pix; float r0, r1, ar; geom(c0, c1, k, pix, r0, r1, ar);
            meta[2*k] = r0; meta[2*k+1] = r1;
        }
        u64 acc[16];
#pragma unroll
        for (int p = 0; p < 16; p++)
            acc[p] = pack2(sm[MS_BM1+jh+2*p], sm[MS_BM1+jh+2*p+1]);
        for (int i = 0; i < 33; i++) {
            float m = meta[i]; u64 mm = pack2(m, m);
            const ulonglong2* wp = (const ulonglong2*)(sm + MS_WM1 + i*64 + jh);
#pragma unroll
            for (int p = 0; p < 8; p++) {
                ulonglong2 w = wp[p];
                ffma2(acc[2*p], mm, w.x); ffma2(acc[2*p+1], mm, w.y);
            }
        }
#pragma unroll
        for (int p = 0; p < 16; p++) {
            float a, b; unpack2(acc[p], a, b);
            sm[MS_H + (jh+2*p)*132 + ql] = fmaxf(a, 0.f);
            sm[MS_H + (jh+2*p+1)*132 + ql] = fmaxf(b, 0.f);
        }
    }

    const int qt = t>>4, nt = t&15;
    const int q0 = qt*8;
    const int qg = blockIdx.x*128 + q0;
    for (int nb = 0; nb < 8; nb++) {
        __syncthreads();
        for (int i = t; i < 2048; i += 256) {
            int c = i>>5, n4 = (i&31)*4;
            *(float4*)(sm + MS_WC + c*128 + n4) = *(const float4*)(w_m2 + c*1024 + nb*128 + n4);
        }
        if (t < 32) *(float4*)(sm + MS_BM2 + t*4) = *(const float4*)(b_m2 + nb*128 + t*4);
        __syncthreads();
        u64 acc[4][8];
#pragma unroll
        for (int p = 0; p < 4; p++)
#pragma unroll
            for (int j = 0; j < 8; j++) acc[p][j] = 0ull;
        for (int c = 0; c < 64; c++) {
            ulonglong2 xA = *(const ulonglong2*)(sm + MS_H + c*132 + q0);
            ulonglong2 xB = *(const ulonglong2*)(sm + MS_H + c*132 + q0 + 4);
            float4 wa = *(const float4*)(sm + MS_WC + c*128 + nt*4);
            float4 wb = *(const float4*)(sm + MS_WC + c*128 + 64 + nt*4);
            u64 wd[8];
            wd[0]=pack2(wa.x,wa.x); wd[1]=pack2(wa.y,wa.y); wd[2]=pack2(wa.z,wa.z); wd[3]=pack2(wa.w,wa.w);
            wd[4]=pack2(wb.x,wb.x); wd[5]=pack2(wb.y,wb.y); wd[6]=pack2(wb.z,wb.z); wd[7]=pack2(wb.w,wb.w);
#pragma unroll
            for (int j = 0; j < 8; j++) {
                ffma2(acc[0][j], xA.x, wd[j]);
                ffma2(acc[1][j], xA.y, wd[j]);
                ffma2(acc[2][j], xB.x, wd[j]);
                ffma2(acc[3][j], xB.y, wd[j]);
            }
        }
#pragma unroll
        for (int p = 0; p < 4; p++) {
            float4 lo0, hi0, lo1, hi1;
            float* l0 = (float*)&lo0; float* h0 = (float*)&hi0;
            float* l1 = (float*)&lo1; float* h1 = (float*)&hi1;
#pragma unroll
            for (int j = 0; j < 4; j++) {
                float a, b; unpack2(acc[p][j], a, b);
                float bz = sm[MS_BM2 + nt*4 + j];
                l0[j] = a + bz; h0[j] = b + bz;
                unpack2(acc[p][4+j], a, b);
                bz = sm[MS_BM2 + 64 + nt*4 + j];
                l1[j] = a + bz; h1[j] = b + bz;
            }
            size_t r0o = (size_t)(qg + 2*p)*1024 + nb*128 + nt*4;
            size_t r1o = (size_t)(qg + 2*p + 1)*1024 + nb*128 + nt*4;
            *(float4*)(g_mod + r0o) = lo0;       *(float4*)(g_mod + r0o + 64) = lo1;
            *(float4*)(g_mod + r1o) = hi0;       *(float4*)(g_mod + r1o + 64) = hi1;
        }
    }
}

// ---------------- imnet kernel (R13 + new feat layout reads) ----------------
#define IS_X    0
#define IS_WT   9240
#define IS_BI1  13720
#define IS_WI2  13784
#define IS_AREA 14040
#define IS_TOT  14168
#define IS_BYTES (IS_TOT*4)
#define IS_PRED 0
#define IS_PW   4096

__global__ void __launch_bounds__(128, 4) imnet_kernel(
    const float* __restrict__ inp, const float* __restrict__ coord,
    const float* __restrict__ cell, const float* __restrict__ w_i1,
    const float* __restrict__ b_i1, const float* __restrict__ w_i2,
    const float* __restrict__ b_i2, float* __restrict__ out) {
    extern __shared__ float sm[];
    const int t = threadIdx.x;
    for (int i = t; i < 1120; i += 128)
        ((float4*)(sm + IS_WT))[i] = ((const float4*)w_i1)[i];
    if (t < 64) {
        sm[IS_BI1+t] = b_i1[t];
        float4 v; v.x = w_i2[t*3]; v.y = w_i2[t*3+1]; v.z = w_i2[t*3+2]; v.w = 0.f;
        *(float4*)(sm + IS_WI2 + t*4) = v;
    }
    const int qi = t>>4, k = t&15;
    const int rt = t>>3, nt = t&7;
    const int r0 = rt*8;

    for (int tile = 0; tile < 2; tile++) {
        if (tile) __syncthreads();
        const int q = blockIdx.x*16 + tile*8 + qi, b = q>>15;

        // ---- stage mod[8q][1024] into X region, coalesced ----
        {
            const float4* msrc =
                (const float4*)(g_mod + (size_t)(blockIdx.x*16 + tile*8)*1024);
            float4* mdst = (float4*)(sm + IS_X);
#pragma unroll
            for (int i = 0; i < 16; i++) mdst[t + i*128] = msrc[t + i*128];
        }
        __syncthreads();

        float modr[64];
#pragma unroll
        for (int c = 0; c < 64; c++) modr[c] = sm[IS_X + qi*1024 + c*16 + k];
        __syncthreads();

        // ---- build X row ----
        {
            float c0 = coord[2*q], c1 = coord[2*q+1];
            float relc = __fmul_rn(cell[2*q], 96.f);
            int pix; float rel0, rel1, area;
            geom(c0, c1, k, pix, rel0, rel1, area);
            sm[IS_AREA + t] = area;
            int iy = pix / WD, ix = pix - iy*WD;
            // feat layout [b][y][c4][x][4c]; chunk stride = WD*4 floats
            const float* fbase = g_feat + (size_t)b*HWP*64
                               + ((size_t)iy*16*WD + ix)*4;
#pragma unroll
            for (int g = 0; g < 16; g++) {
                float4 f = *(const float4*)(fbase + (size_t)g*WD*4);
                sm[IS_X + (4*g+0)*132 + t] = f.x * modr[4*g+0];
                sm[IS_X + (4*g+1)*132 + t] = f.y * modr[4*g+1];
                sm[IS_X + (4*g+2)*132 + t] = f.z * modr[4*g+2];
                sm[IS_X + (4*g+3)*132 + t] = f.w * modr[4*g+3];
            }
            sm[IS_X + 64*132 + t] = inp[(b*3+0)*HWP + pix];
            sm[IS_X + 65*132 + t] = inp[(b*3+1)*HWP + pix];
            sm[IS_X + 66*132 + t] = inp[(b*3+2)*HWP + pix];
            sm[IS_X + 67*132 + t] = rel0;
            sm[IS_X + 68*132 + t] = rel1;
            sm[IS_X + 69*132 + t] = relc;
        }
        __syncthreads();

        // ---- GEMM 128r x 64n, 8r x 8n tiles (frozen) ----
        u64 acc[4][8];
#pragma unroll
        for (int p = 0; p < 4; p++)
#pragma unroll
            for (int j = 0; j < 8; j++) acc[p][j] = 0ull;
#pragma unroll 2
        for (int c = 0; c < 70; c++) {
            ulonglong2 xA = *(const ulonglong2*)(sm + IS_X + c*132 + r0);
            ulonglong2 xB = *(const ulonglong2*)(sm + IS_X + c*132 + r0 + 4);
            float4 wa = *(const float4*)(sm + IS_WT + c*64 + nt*4);
            float4 wb = *(const float4*)(sm + IS_WT + c*64 + 32 + nt*4);
            u64 wd[8];
            wd[0]=pack2(wa.x,wa.x); wd[1]=pack2(wa.y,wa.y); wd[2]=pack2(wa.z,wa.z); wd[3]=pack2(wa.w,wa.w);
            wd[4]=pack2(wb.x,wb.x); wd[5]=pack2(wb.y,wb.y); wd[6]=pack2(wb.z,wb.z); wd[7]=pack2(wb.w,wb.w);
#pragma unroll
            for (int j = 0; j < 8; j++) {
                ffma2(acc[0][j], xA.x, wd[j]);
                ffma2(acc[1][j], xA.y, wd[j]);
                ffma2(acc[2][j], xB.x, wd[j]);
                ffma2(acc[3][j], xB.y, wd[j]);
            }
        }
        __syncthreads();

        // ---- layer 2 partials ----
#pragma unroll
        for (int p = 0; p < 4; p++) {
            float pr0[3] = {0.f,0.f,0.f}, pr1[3] = {0.f,0.f,0.f};
#pragma unroll
            for (int j = 0; j < 8; j++) {
                int n = (j < 4) ? (nt*4 + j) : (32 + nt*4 + j - 4);
                float a, bv; unpack2(acc[p][j], a, bv);
                float bz = sm[IS_BI1 + n];
                float a0 = fmaxf(a + bz, 0.f), a1 = fmaxf(bv + bz, 0.f);
                float4 w2 = *(const float4*)(sm + IS_WI2 + n*4);
                pr0[0] = fmaf(a0, w2.x, pr0[0]); pr0[1] = fmaf(a0, w2.y, pr0[1]); pr0[2] = fmaf(a0, w2.z, pr0[2]);
                pr1[0] = fmaf(a1, w2.x, pr1[0]); pr1[1] = fmaf(a1, w2.y, pr1[1]); pr1[2] = fmaf(a1, w2.z, pr1[2]);
            }
            float4 v0; v0.x = pr0[0]; v0.y = pr0[1]; v0.z = pr0[2]; v0.w = 0.f;
            float4 v1; v1.x = pr1[0]; v1.y = pr1[1]; v1.z = pr1[2]; v1.w = 0.f;
            *(float4*)(sm + IS_PRED + ((r0 + 2*p)*8 + nt)*4) = v0;
            *(float4*)(sm + IS_PRED + ((r0 + 2*p + 1)*8 + nt)*4) = v1;
        }
        __syncthreads();

        // ---- per-row reduce + area blend ----
        {
            float s0 = 0.f, s1 = 0.f, s2 = 0.f;
#pragma unroll
            for (int n = 0; n < 8; n++) {
                float4 v = *(const float4*)(sm + IS_PRED + (t*8 + n)*4);
                s0 += v.x; s1 += v.y; s2 += v.z;
            }
            float tot = 0.f;
#pragma unroll
            for (int kk = 0; kk < 16; kk++) tot += sm[IS_AREA + qi*16 + kk];
            float wgt = __fdiv_rn(sm[IS_AREA + qi*16 + (15-k)], tot);
            float4 v; v.x = s0*wgt; v.y = s1*wgt; v.z = s2*wgt; v.w = 0.f;
            __syncthreads();
            *(float4*)(sm + IS_PW + t*4) = v;
        }
        __syncthreads();
        if (t < 24) {
            int qi2 = t/3, ch = t%3;
            float s = 0.f;
#pragma unroll
            for (int kk = 0; kk < 16; kk++) s += sm[IS_PW + (qi2*16 + kk)*4 + ch];
            out[(size_t)(blockIdx.x*16 + tile*8 + qi2)*3 + ch] = s;
        }
    }
}

extern "C" void kernel_launch(void* const* d_in, const int* in_sizes, int n_in,
                              void* d_out, int out_size) {
    const float* inp   = (const float*)d_in[0];
    const float* coord = (const float*)d_in[1];
    const float* cell  = (const float*)d_in[2];
    const float* w_enc = (const float*)d_in[3];
    const float* b_enc = (const float*)d_in[4];
    const float* w_m1  = (const float*)d_in[5];
    const float* b_m1  = (const float*)d_in[6];
    const float* w_m2  = (const float*)d_in[7];
    const float* b_m2  = (const float*)d_in[8];
    const float* w_i1  = (const float*)d_in[9];
    const float* b_i1  = (const float*)d_in[10];
    const float* w_i2  = (const float*)d_in[11];
    const float* b_i2  = (const float*)d_in[12];
    float* out = (float*)d_out;

    cudaFuncSetAttribute(meta_kernel, cudaFuncAttributeMaxDynamicSharedMemorySize, MS_BYTES);
    cudaFuncSetAttribute(imnet_kernel, cudaFuncAttributeMaxDynamicSharedMemorySize, IS_BYTES);

    conv_kernel<<<(2*HWP*16 + 255)/256, 256>>>(inp, w_enc, b_enc);
    meta_kernel<<<512, 256, MS_BYTES>>>(coord, cell, w_m1, b_m1, w_m2, b_m2);
    imnet_kernel<<<4096, 128, IS_BYTES>>>(inp, coord, cell, w_i1, b_i1, w_i2, b_i2, out);
}